// round 13
// baseline (speedup 1.0000x reference)
#include <cuda_runtime.h>
#include <cuda_fp16.h>
#include <cfloat>
#include <cstdint>

// Problem constants
#define B_    8
#define S_    4096
#define D_    1024
#define DS_   64
#define MTOT  32768      // B_*S_
#define NU    960        // used neurons: 512+256+128+64 (N_KNOW unused)
#define NBLK  512        // 64-row blocks

// Scratch (device globals — allocation-free per harness rules)
__device__ float g_wpart[NBLK * NU];               // per-block partial w [512][960]

// ---------------- bf16 triple-split helpers ----------------
__device__ __forceinline__ uint32_t cvt2bf(float lo, float hi) {
    uint32_t r;
    asm("cvt.rn.bf16x2.f32 %0, %2, %1;" : "=r"(r) : "f"(lo), "f"(hi));
    return r;
}
__device__ __forceinline__ float2 bf2f(uint32_t p) {
    return make_float2(__uint_as_float(p << 16), __uint_as_float(p & 0xffff0000u));
}
__device__ __forceinline__ void split3(float a, float b,
                                       uint32_t& u0, uint32_t& u1, uint32_t& u2) {
    u0 = cvt2bf(a, b);
    float2 f0 = bf2f(u0);
    float ra = a - f0.x, rb = b - f0.y;
    u1 = cvt2bf(ra, rb);
    float2 f1 = bf2f(u1);
    u2 = cvt2bf(ra - f1.x, rb - f1.y);
}

// ---------------- warp-level bf16 HMMA (baseline PTX, sm_80+) ----------------
__device__ __forceinline__ void mma_bf16(float* c, const uint32_t* a, const uint32_t* b) {
    asm volatile(
        "mma.sync.aligned.m16n8k16.row.col.f32.bf16.bf16.f32 "
        "{%0,%1,%2,%3}, {%4,%5,%6,%7}, {%8,%9}, {%0,%1,%2,%3};"
        : "+f"(c[0]), "+f"(c[1]), "+f"(c[2]), "+f"(c[3])
        : "r"(a[0]), "r"(a[1]), "r"(a[2]), "r"(a[3]), "r"(b[0]), "r"(b[1]));
}

// ---------------- fast exp on the FMA pipe ----------------
__device__ __forceinline__ float fexp(float x) {
    float y  = x * 1.4426950408889634f;
    float fi = rintf(y);
    float f  = y - fi;
    float p  = 1.54035304e-4f;
    p = __fmaf_rn(p, f, 1.33335581e-3f);
    p = __fmaf_rn(p, f, 9.61812911e-3f);
    p = __fmaf_rn(p, f, 5.55041087e-2f);
    p = __fmaf_rn(p, f, 2.40226507e-1f);
    p = __fmaf_rn(p, f, 6.93147181e-1f);
    p = __fmaf_rn(p, f, 1.0f);
    int i = (int)fi;
    return p * __int_as_float((i + 127) << 23);
}

// ================= smem layout (bytes) =================
//   snorm [960]f       @ 0      (3840)
//   sZ2  [2][64][4]f   @ 3840   (2048)   per-n-half row Z partials
//   scoef[64][4]f      @ 5888   (1024)
//   XW   @ 6912 (55296): phase-1 x splits [3][64][144] + W splits [3][64][144]
//                        phase-2 B ping-pong [2][3][64][144] (aliased)
//   E    @ 62208 (123904): fp16 E [64 rows][968 cols] (stride 1936 B)
//                        phase-1 hs splits [3][64][144] alias the first 27648 B
#define SN_B   0
#define SZ2_B  3840
#define SC_B   5888
#define XW_B   6912
#define E_B    62208
#define ROWB   144        // 72 bf16 per row (64 + 8 pad)
#define ESTRIDE 1936      // 968 halves per row (964 would misalign; 968 -> 484 words, mod32=4)
#define SMEM_BYTES 186112

__global__ void k_dummy() {}

__global__ __launch_bounds__(256, 1) void k_mega(const float* __restrict__ x,
                                                 const float* __restrict__ W,
                                                 const float* __restrict__ bias,
                                                 const float* __restrict__ imp,
                                                 const float* __restrict__ emb) {
    extern __shared__ __align__(16) char smc[];
    float* snorm = (float*)(smc + SN_B);
    float* sZ2   = (float*)(smc + SZ2_B);   // [(h*64+row)*4+g]
    float* scoef = (float*)(smc + SC_B);

    int tid  = threadIdx.x;
    int wid  = tid >> 5;
    int lane = tid & 31;
    int mw   = wid & 3;            // m-tile (16 rows each)
    int nh   = wid >> 2;           // n-half (32 cols each)
    int row0 = mw * 16 + (lane >> 2);
    int kofs = (lane & 3) * 2;
    int m0   = blockIdx.x * 64;

    const int pa[6] = {0, 0, 1, 0, 1, 2};
    const int pb[6] = {0, 1, 0, 2, 1, 0};

    // ---- embedding inverse norms ----
    for (int n = tid; n < NU; n += 256) {
        const float4* er = (const float4*)(emb + (size_t)n * DS_);
        float ss = 0.f;
#pragma unroll
        for (int j = 0; j < 16; j++) {
            float4 v = er[j];
            ss += v.x * v.x + v.y * v.y + v.z * v.z + v.w * v.w;
        }
        snorm[n] = rsqrtf(ss);
    }

    // ---------- Phase 1: h = x @ W^T via bf16x6 HMMA, 16 k-chunks of 64 ----------
    float C[4][4];
#pragma unroll
    for (int nt = 0; nt < 4; nt++)
#pragma unroll
        for (int j = 0; j < 4; j++) C[nt][j] = 0.f;

    float4 xv[4], wv[4];
#pragma unroll
    for (int it = 0; it < 4; ++it) {
        int i = it * 256 + tid; int r = i >> 4; int c = i & 15;
        xv[it] = *(const float4*)(x + (size_t)(m0 + r) * D_ + c * 4);
        wv[it] = *(const float4*)(W + (size_t)r * D_ + c * 4);
    }

    for (int ch = 0; ch < 16; ++ch) {
        // commit current chunk (triple-split) to smem
#pragma unroll
        for (int it = 0; it < 4; ++it) {
            int i = it * 256 + tid; int r = i >> 4; int c = i & 15;
            uint32_t p0, p1, p2, q0, q1, q2;
            uint32_t off = (uint32_t)(r * ROWB + c * 8);
            split3(xv[it].x, xv[it].y, p0, p1, p2);
            split3(xv[it].z, xv[it].w, q0, q1, q2);
            *(uint2*)(smc + XW_B + 0 * 9216 + off) = make_uint2(p0, q0);
            *(uint2*)(smc + XW_B + 1 * 9216 + off) = make_uint2(p1, q1);
            *(uint2*)(smc + XW_B + 2 * 9216 + off) = make_uint2(p2, q2);
            split3(wv[it].x, wv[it].y, p0, p1, p2);
            split3(wv[it].z, wv[it].w, q0, q1, q2);
            *(uint2*)(smc + XW_B + 27648 + 0 * 9216 + off) = make_uint2(p0, q0);
            *(uint2*)(smc + XW_B + 27648 + 1 * 9216 + off) = make_uint2(p1, q1);
            *(uint2*)(smc + XW_B + 27648 + 2 * 9216 + off) = make_uint2(p2, q2);
        }
        __syncthreads();
        // prefetch next chunk
        if (ch + 1 < 16) {
            int k0 = (ch + 1) * 64;
#pragma unroll
            for (int it = 0; it < 4; ++it) {
                int i = it * 256 + tid; int r = i >> 4; int c = i & 15;
                xv[it] = *(const float4*)(x + (size_t)(m0 + r) * D_ + k0 + c * 4);
                wv[it] = *(const float4*)(W + (size_t)r * D_ + k0 + c * 4);
            }
        }
#pragma unroll
        for (int ks = 0; ks < 4; ++ks) {
            uint32_t Afc[3][4];
#pragma unroll
            for (int s = 0; s < 3; s++) {
                const char* base = smc + XW_B + s * 9216;
                Afc[s][0] = *(const uint32_t*)(base + row0 * ROWB       + (ks * 16 + kofs) * 2);
                Afc[s][1] = *(const uint32_t*)(base + (row0 + 8) * ROWB + (ks * 16 + kofs) * 2);
                Afc[s][2] = *(const uint32_t*)(base + row0 * ROWB       + (ks * 16 + 8 + kofs) * 2);
                Afc[s][3] = *(const uint32_t*)(base + (row0 + 8) * ROWB + (ks * 16 + 8 + kofs) * 2);
            }
#pragma unroll
            for (int nt = 0; nt < 4; ++nt) {
                uint32_t Bf[3][2];
                int nr = nh * 32 + nt * 8 + (lane >> 2);
#pragma unroll
                for (int s = 0; s < 3; s++) {
                    const char* base = smc + XW_B + 27648 + s * 9216;
                    Bf[s][0] = *(const uint32_t*)(base + nr * ROWB + (ks * 16 + kofs) * 2);
                    Bf[s][1] = *(const uint32_t*)(base + nr * ROWB + (ks * 16 + 8 + kofs) * 2);
                }
#pragma unroll
                for (int p = 0; p < 6; ++p)
                    mma_bf16(C[nt], Afc[pa[p]], Bf[pb[p]]);
            }
        }
        __syncthreads();
    }

    // ---------- epilogue: +bias, triple-split h into hs (aliases E region) ----------
#pragma unroll
    for (int nt = 0; nt < 4; ++nt) {
        int colb = nh * 32 + nt * 8 + kofs;
        float b0 = bias[colb], b1 = bias[colb + 1];
        uint32_t u0, u1, u2, v0, v1, v2;
        split3(C[nt][0] + b0, C[nt][1] + b1, u0, u1, u2);
        split3(C[nt][2] + b0, C[nt][3] + b1, v0, v1, v2);
        *(uint32_t*)(smc + E_B + 0 * 9216 + row0 * ROWB + colb * 2) = u0;
        *(uint32_t*)(smc + E_B + 1 * 9216 + row0 * ROWB + colb * 2) = u1;
        *(uint32_t*)(smc + E_B + 2 * 9216 + row0 * ROWB + colb * 2) = u2;
        *(uint32_t*)(smc + E_B + 0 * 9216 + (row0 + 8) * ROWB + colb * 2) = v0;
        *(uint32_t*)(smc + E_B + 1 * 9216 + (row0 + 8) * ROWB + colb * 2) = v1;
        *(uint32_t*)(smc + E_B + 2 * 9216 + (row0 + 8) * ROWB + colb * 2) = v2;
    }
    __syncthreads();

    // ---------- load A fragments (resident; hs freed afterwards) ----------
    uint32_t Af[3][4][4];
#pragma unroll
    for (int s = 0; s < 3; s++) {
        const char* base = smc + E_B + s * 9216;
#pragma unroll
        for (int ks = 0; ks < 4; ks++) {
            Af[s][ks][0] = *(const uint32_t*)(base + row0 * ROWB       + (ks * 16 + kofs) * 2);
            Af[s][ks][1] = *(const uint32_t*)(base + (row0 + 8) * ROWB + (ks * 16 + kofs) * 2);
            Af[s][ks][2] = *(const uint32_t*)(base + row0 * ROWB       + (ks * 16 + 8 + kofs) * 2);
            Af[s][ks][3] = *(const uint32_t*)(base + (row0 + 8) * ROWB + (ks * 16 + 8 + kofs) * 2);
        }
    }
    __syncthreads();   // hs reads done; E region free for phase-2 writes

    // ---------- Phase 2: 15 n-slabs of 64; E -> smem fp16; Z in fp32 ----------
    auto load_B = [&](int t, int bq) {
        int n0 = t * 64;
        char* dst = smc + XW_B + bq * 27648;
#pragma unroll
        for (int it = 0; it < 4; ++it) {
            int i = it * 256 + tid; int n = i >> 4; int c = i & 15;
            float s = snorm[n0 + n];
            float4 v = *(const float4*)(emb + (size_t)(n0 + n) * DS_ + c * 4);
            uint32_t p0, p1, p2, q0, q1, q2;
            split3(v.x * s, v.y * s, p0, p1, p2);
            split3(v.z * s, v.w * s, q0, q1, q2);
            uint32_t off = (uint32_t)(n * ROWB + c * 8);
            *(uint2*)(dst + 0 * 9216 + off) = make_uint2(p0, q0);
            *(uint2*)(dst + 1 * 9216 + off) = make_uint2(p1, q1);
            *(uint2*)(dst + 2 * 9216 + off) = make_uint2(p2, q2);
        }
    };

    float zacc[2][4] = {{0.f, 0.f, 0.f, 0.f}, {0.f, 0.f, 0.f, 0.f}};

    load_B(0, 0);
    __syncthreads();

    for (int t = 0; t < 15; ++t) {
        if (t + 1 < 15) load_B(t + 1, (t + 1) & 1);
        const char* bb = smc + XW_B + (t & 1) * 27648;
        int g = (t < 8) ? 0 : (t < 12) ? 1 : (t < 14) ? 2 : 3;

#pragma unroll
        for (int nt = 0; nt < 4; ++nt) {
            uint32_t Bf[3][4][2];
            int nr = nh * 32 + nt * 8 + (lane >> 2);
#pragma unroll
            for (int s = 0; s < 3; s++) {
                const char* base = bb + s * 9216;
#pragma unroll
                for (int ks = 0; ks < 4; ks++) {
                    Bf[s][ks][0] = *(const uint32_t*)(base + nr * ROWB + (ks * 16 + kofs) * 2);
                    Bf[s][ks][1] = *(const uint32_t*)(base + nr * ROWB + (ks * 16 + 8 + kofs) * 2);
                }
            }
            float Cp[6][4];
#pragma unroll
            for (int p = 0; p < 6; p++)
#pragma unroll
                for (int j = 0; j < 4; j++) Cp[p][j] = 0.f;
#pragma unroll
            for (int ks = 0; ks < 4; ks++)
#pragma unroll
                for (int p = 0; p < 6; p++)
                    mma_bf16(Cp[p], Af[pa[p]][ks], Bf[pb[p]][ks]);

            float c0 = ((Cp[0][0] + Cp[1][0]) + (Cp[2][0] + Cp[3][0])) + (Cp[4][0] + Cp[5][0]);
            float c1 = ((Cp[0][1] + Cp[1][1]) + (Cp[2][1] + Cp[3][1])) + (Cp[4][1] + Cp[5][1]);
            float c2 = ((Cp[0][2] + Cp[1][2]) + (Cp[2][2] + Cp[3][2])) + (Cp[4][2] + Cp[5][2]);
            float c3 = ((Cp[0][3] + Cp[1][3]) + (Cp[2][3] + Cp[3][3])) + (Cp[4][3] + Cp[5][3]);

            float e0 = fexp(c0), e1 = fexp(c1);
            float e2 = fexp(c2), e3 = fexp(c3);
            int col = t * 64 + nh * 32 + nt * 8 + kofs;
            __half2 h01 = __float22half2_rn(make_float2(e0, e1));
            __half2 h23 = __float22half2_rn(make_float2(e2, e3));
            *(uint32_t*)(smc + E_B + row0 * ESTRIDE + col * 2)       = *(uint32_t*)&h01;
            *(uint32_t*)(smc + E_B + (row0 + 8) * ESTRIDE + col * 2) = *(uint32_t*)&h23;
            zacc[0][g] += e0 + e1;
            zacc[1][g] += e2 + e3;
        }
        __syncthreads();   // buf t consumed; buf t+1 committed
    }

    // ---------- row Z: quad-reduce -> sZ2 (per n-half), combine -> coef ----------
#pragma unroll
    for (int h = 0; h < 2; h++)
#pragma unroll
        for (int g = 0; g < 4; g++) {
            float z = zacc[h][g];
            z += __shfl_xor_sync(0xffffffffu, z, 1);
            z += __shfl_xor_sync(0xffffffffu, z, 2);
            zacc[h][g] = z;
        }
    if ((lane & 3) == 0) {
#pragma unroll
        for (int g = 0; g < 4; g++) {
            sZ2[(nh * 64 + row0) * 4 + g]       = zacc[0][g];
            sZ2[(nh * 64 + row0 + 8) * 4 + g]   = zacc[1][g];
        }
    }
    __syncthreads();
    if (tid < 64) {
        float im = imp[m0 + tid];
#pragma unroll
        for (int g = 0; g < 4; g++) {
            float z = sZ2[tid * 4 + g] + sZ2[(64 + tid) * 4 + g];
            scoef[tid * 4 + g] = im * __frcp_rn(z);
        }
    }
    __syncthreads();

    // ---------- Phase 4: accum from smem E -> wpart[bx][960] ----------
    if (tid < 240) {
        int n4 = tid * 4;
        int g = (n4 < 512) ? 0 : (n4 < 768) ? 1 : (n4 < 896) ? 2 : 3;
        float4 a = make_float4(0.f, 0.f, 0.f, 0.f);
#pragma unroll 8
        for (int r = 0; r < 64; r++) {
            float cf = scoef[r * 4 + g];
            uint2 hh = *(const uint2*)(smc + E_B + r * ESTRIDE + n4 * 2);
            float2 f01 = __half22float2(*reinterpret_cast<__half2*>(&hh.x));
            float2 f23 = __half22float2(*reinterpret_cast<__half2*>(&hh.y));
            a.x += cf * f01.x; a.y += cf * f01.y;
            a.z += cf * f23.x; a.w += cf * f23.y;
        }
        *(float4*)(g_wpart + (size_t)blockIdx.x * NU + n4) = a;
    }
}

// ---------------- k_final: parallel rank-select top-k ----------------
__global__ __launch_bounds__(512) void k_final(float* __restrict__ out) {
    __shared__ __align__(16) float sw[NU];
    __shared__ unsigned bq[16];
    __shared__ unsigned bv[8];
    int b = blockIdx.x, t = threadIdx.x;
    int w = t >> 5, lane = t & 31;

    for (int n = t; n < NU; n += 512) {
        float a = 0.f;
#pragma unroll
        for (int c = 0; c < 64; c++) a += g_wpart[(size_t)(b * 64 + c) * NU + n];
        sw[n] = a;
    }
    __syncthreads();

    const float4* s4 = (const float4*)sw;
    bool selq;
    {
        float v = sw[t]; int r = 0;
#pragma unroll 4
        for (int j4 = 0; j4 < 128; j4++) {
            float4 o = s4[j4]; int j = j4 * 4;
            r += (o.x > v) || (o.x == v && j < t);
            r += (o.y > v) || (o.y == v && j + 1 < t);
            r += (o.z > v) || (o.z == v && j + 2 < t);
            r += (o.w > v) || (o.w == v && j + 3 < t);
        }
        selq = (r < 64);
    }
    bool selv = false, selr = false, selval = false;
    if (t < 256) {
        float v = sw[512 + t]; int r = 0;
#pragma unroll 4
        for (int j4 = 0; j4 < 64; j4++) {
            float4 o = s4[128 + j4]; int j = j4 * 4;
            r += (o.x > v) || (o.x == v && j < t);
            r += (o.y > v) || (o.y == v && j + 1 < t);
            r += (o.z > v) || (o.z == v && j + 2 < t);
            r += (o.w > v) || (o.w == v && j + 3 < t);
        }
        selv = (r < 32);
    }
    if (t < 128) {
        float v = sw[768 + t]; int r = 0;
#pragma unroll 4
        for (int j4 = 0; j4 < 32; j4++) {
            float4 o = s4[192 + j4]; int j = j4 * 4;
            r += (o.x > v) || (o.x == v && j < t);
            r += (o.y > v) || (o.y == v && j + 1 < t);
            r += (o.z > v) || (o.z == v && j + 2 < t);
            r += (o.w > v) || (o.w == v && j + 3 < t);
        }
        selr = (r < 16);
    }
    if (t < 64) {
        float v = sw[896 + t]; int r = 0;
#pragma unroll
        for (int j4 = 0; j4 < 16; j4++) {
            float4 o = s4[224 + j4]; int j = j4 * 4;
            r += (o.x > v) || (o.x == v && j < t);
            r += (o.y > v) || (o.y == v && j + 1 < t);
            r += (o.z > v) || (o.z == v && j + 2 < t);
            r += (o.w > v) || (o.w == v && j + 3 < t);
        }
        selval = (r < 3);
    }

    unsigned mq = __ballot_sync(0xffffffffu, selq);
    unsigned mv = __ballot_sync(0xffffffffu, selv);
    if (lane == 0) {
        bq[w] = mq;
        if (w < 8) bv[w] = mv;
    }
    __syncthreads();

    if (selq) {
        int pos = 0;
        for (int i = 0; i < w; i++) pos += __popc(bq[i]);
        pos += __popc(mq & ((1u << lane) - 1u));
        out[b * 64 + pos] = (float)t;
    }
    if (selv) {
        int pos = 0;
        for (int i = 0; i < w; i++) pos += __popc(bv[i]);
        pos += __popc(mv & ((1u << lane) - 1u));
        out[512 + b * 32 + pos] = (float)t;
    }
    if (t < 128) {
        float val = selr ? sw[768 + t] : 0.f;
        out[768  + b * 128 + t] = val;
        out[1792 + b * 128 + t] = val;
    }
    if (t < 64) {
        out[2816 + b * 64 + t] = selval ? sw[896 + t] : 0.f;
    }
}

// ---------------- launch ----------------
// Launch order [dummy, k_mega, k_final, dummy] = period 4 so ncu's `-s 5 -c 1`
// (6th launch) lands on k_mega — finally a profile of the main kernel.
extern "C" void kernel_launch(void* const* d_in, const int* in_sizes, int n_in,
                              void* d_out, int out_size) {
    const float* x    = (const float*)d_in[0];
    const float* imp  = (const float*)d_in[1];
    const float* W    = (const float*)d_in[2];
    const float* bias = (const float*)d_in[3];
    const float* emb  = (const float*)d_in[4];
    float* out = (float*)d_out;

    static bool attr_set = false;
    if (!attr_set) {
        cudaFuncSetAttribute(k_mega, cudaFuncAttributeMaxDynamicSharedMemorySize,
                             SMEM_BYTES);
        attr_set = true;
    }

    k_dummy<<<1, 32>>>();
    k_mega<<<NBLK, 256, SMEM_BYTES>>>(x, W, bias, imp, emb);
    k_final<<<B_, 512>>>(out);
    k_dummy<<<1, 32>>>();
}

// round 15
// speedup vs baseline: 1.6172x; 1.6172x over previous
#include <cuda_runtime.h>
#include <cuda_fp16.h>
#include <cfloat>
#include <cstdint>

// Problem constants
#define B_    8
#define S_    4096
#define D_    1024
#define DS_   64
#define MTOT  32768      // B_*S_
#define NU    960        // used neurons: 512+256+128+64 (N_KNOW unused)
#define NBLK  256        // 128-row blocks

// Scratch (device globals — allocation-free per harness rules)
__device__ __half g_Eh[(size_t)MTOT * NU];         // exp(logits) fp16 [32768][960]
__device__ float  g_wpart[NBLK * NU];              // per-block partial w [256][960]

// ---------------- bf16 double-split helpers ----------------
// cvt.rn.bf16x2.f32 d, a, b : a -> high half, b -> low half
__device__ __forceinline__ uint32_t cvt2bf(float lo, float hi) {
    uint32_t r;
    asm("cvt.rn.bf16x2.f32 %0, %2, %1;" : "=r"(r) : "f"(lo), "f"(hi));
    return r;
}
__device__ __forceinline__ float2 bf2f(uint32_t p) {
    return make_float2(__uint_as_float(p << 16), __uint_as_float(p & 0xffff0000u));
}
__device__ __forceinline__ void split2(float a, float b, uint32_t& u0, uint32_t& u1) {
    u0 = cvt2bf(a, b);
    float2 f0 = bf2f(u0);
    u1 = cvt2bf(a - f0.x, b - f0.y);
}

// ---------------- warp-level bf16 HMMA + ldmatrix (baseline PTX) ----------------
__device__ __forceinline__ void mma_bf16(float* c, const uint32_t* a, const uint32_t* b) {
    asm volatile(
        "mma.sync.aligned.m16n8k16.row.col.f32.bf16.bf16.f32 "
        "{%0,%1,%2,%3}, {%4,%5,%6,%7}, {%8,%9}, {%0,%1,%2,%3};"
        : "+f"(c[0]), "+f"(c[1]), "+f"(c[2]), "+f"(c[3])
        : "r"(a[0]), "r"(a[1]), "r"(a[2]), "r"(a[3]), "r"(b[0]), "r"(b[1]));
}
__device__ __forceinline__ void ldsm_x4(uint32_t& r0, uint32_t& r1,
                                        uint32_t& r2, uint32_t& r3, uint32_t addr) {
    asm volatile("ldmatrix.sync.aligned.m8n8.x4.shared.b16 {%0,%1,%2,%3}, [%4];"
        : "=r"(r0), "=r"(r1), "=r"(r2), "=r"(r3) : "r"(addr));
}
__device__ __forceinline__ uint32_t smem_u32(const void* p) {
    uint32_t a;
    asm("{ .reg .u64 t; cvta.to.shared.u64 t, %1; cvt.u32.u64 %0, t; }" : "=r"(a) : "l"(p));
    return a;
}

// ---------------- fast exp on the FMA pipe ----------------
__device__ __forceinline__ float fexp(float x) {
    float y  = x * 1.4426950408889634f;
    float fi = rintf(y);
    float f  = y - fi;
    float p  = 1.54035304e-4f;
    p = __fmaf_rn(p, f, 1.33335581e-3f);
    p = __fmaf_rn(p, f, 9.61812911e-3f);
    p = __fmaf_rn(p, f, 5.55041087e-2f);
    p = __fmaf_rn(p, f, 2.40226507e-1f);
    p = __fmaf_rn(p, f, 6.93147181e-1f);
    p = __fmaf_rn(p, f, 1.0f);
    int i = (int)fi;
    return p * __int_as_float((i + 127) << 23);
}

// ================= smem layout (bytes) =================
//   snorm [960]f  @ 0      (3840)
//   sZ [128][4]f  @ 3840   (2048)
//   scoef[128][4]f@ 5888   (2048)
//   XS @ 7936  (36864): phase-1 x splits [2][128][144]
//                       phase-2 B ping-pong [2][2][64][144] (aliased)
//   WS @ 44800 (18432): phase-1 W splits [2][64][144]
#define SN_B   0
#define SZ_B   3840
#define SC_B   5888
#define XS_B   7936
#define WS_B   44800
#define ROWB   144        // 72 bf16 per row (64 + 8 pad) — ldmatrix conflict-free
#define SMEM_BYTES 63232

__global__ __launch_bounds__(256, 2) void k_mega(const float* __restrict__ x,
                                                 const float* __restrict__ W,
                                                 const float* __restrict__ bias,
                                                 const float* __restrict__ imp,
                                                 const float* __restrict__ emb) {
    extern __shared__ __align__(16) char smc[];
    float* snorm = (float*)(smc + SN_B);
    float* sZ    = (float*)(smc + SZ_B);
    float* scoef = (float*)(smc + SC_B);

    int tid  = threadIdx.x;
    int wid  = tid >> 5;
    int lane = tid & 31;
    int m0   = blockIdx.x * 128;
    int row0 = wid * 16 + (lane >> 2);
    int kofs = (lane & 3) * 2;

    uint32_t sbase = smem_u32(smc);
    // ldmatrix per-lane address components
    int lrow = (lane & 7) + ((lane >> 3) & 1) * 8;   // matrix row within 16-row tile
    int lcolA = (lane >> 4) * 8;                     // A: k-half select (quads 2,3)
    int q = lane >> 3;
    int brow = lane & 7;                             // B: n within 8-row tile
    int bcolq = (q >> 1) * 16 + (q & 1) * 8;         // B: quad -> (ks-in-pair, k-half)

    // ---- embedding inverse norms ----
    for (int n = tid; n < NU; n += 256) {
        const float4* er = (const float4*)(emb + (size_t)n * DS_);
        float ss = 0.f;
#pragma unroll
        for (int j = 0; j < 16; j++) {
            float4 v = er[j];
            ss += v.x * v.x + v.y * v.y + v.z * v.z + v.w * v.w;
        }
        snorm[n] = rsqrtf(ss);
    }

    // ---------- Phase 1: h = x @ W^T via bf16x3 HMMA, 16 k-chunks of 64 ----------
    float C[8][4];
#pragma unroll
    for (int nt = 0; nt < 8; nt++)
#pragma unroll
        for (int j = 0; j < 4; j++) C[nt][j] = 0.f;

    for (int ch = 0; ch < 16; ++ch) {
        int k0 = ch * 64;
        // x chunk [128 m][64 k] double-split -> XS
#pragma unroll
        for (int it = 0; it < 8; ++it) {
            int i = it * 256 + tid; int r = i >> 4; int c = i & 15;
            float4 v = *(const float4*)(x + (size_t)(m0 + r) * D_ + k0 + c * 4);
            uint32_t p0, p1, q0, q1;
            split2(v.x, v.y, p0, p1);
            split2(v.z, v.w, q0, q1);
            uint32_t off = (uint32_t)(r * ROWB + c * 8);
            *(uint2*)(smc + XS_B + 0 * 18432 + off) = make_uint2(p0, q0);
            *(uint2*)(smc + XS_B + 1 * 18432 + off) = make_uint2(p1, q1);
        }
        // W chunk [64 n][64 k] double-split -> WS
#pragma unroll
        for (int it = 0; it < 4; ++it) {
            int i = it * 256 + tid; int r = i >> 4; int c = i & 15;
            float4 v = *(const float4*)(W + (size_t)r * D_ + k0 + c * 4);
            uint32_t p0, p1, q0, q1;
            split2(v.x, v.y, p0, p1);
            split2(v.z, v.w, q0, q1);
            uint32_t off = (uint32_t)(r * ROWB + c * 8);
            *(uint2*)(smc + WS_B + 0 * 9216 + off) = make_uint2(p0, q0);
            *(uint2*)(smc + WS_B + 1 * 9216 + off) = make_uint2(p1, q1);
        }
        __syncthreads();

        // A fragments for this chunk: [2 splits][4 ks][4 regs]
        uint32_t Afc[2][4][4];
#pragma unroll
        for (int s = 0; s < 2; s++)
#pragma unroll
            for (int ks = 0; ks < 4; ks++)
                ldsm_x4(Afc[s][ks][0], Afc[s][ks][1], Afc[s][ks][2], Afc[s][ks][3],
                        sbase + XS_B + s * 18432
                              + (uint32_t)((wid * 16 + lrow) * ROWB + (ks * 16 + lcolA) * 2));

#pragma unroll
        for (int nt = 0; nt < 8; ++nt) {
            uint32_t Bf[2][4][2];
#pragma unroll
            for (int s = 0; s < 2; s++)
#pragma unroll
                for (int kp = 0; kp < 2; kp++)
                    ldsm_x4(Bf[s][2 * kp][0], Bf[s][2 * kp][1],
                            Bf[s][2 * kp + 1][0], Bf[s][2 * kp + 1][1],
                            sbase + WS_B + s * 9216
                                  + (uint32_t)((nt * 8 + brow) * ROWB
                                               + (kp * 32 + bcolq) * 2));
#pragma unroll
            for (int ks = 0; ks < 4; ++ks) {
                mma_bf16(C[nt], Afc[0][ks], Bf[0][ks]);
                mma_bf16(C[nt], Afc[0][ks], Bf[1][ks]);
                mma_bf16(C[nt], Afc[1][ks], Bf[0][ks]);
            }
        }
        __syncthreads();
    }

    // ---------- bias + in-register convert: C frags -> phase-2 A frags ----------
    uint32_t Af[2][4][4];
#pragma unroll
    for (int ks = 0; ks < 4; ++ks) {
        int nt0 = 2 * ks, nt1 = 2 * ks + 1;
        float b00 = bias[nt0 * 8 + kofs], b01 = bias[nt0 * 8 + kofs + 1];
        float b10 = bias[nt1 * 8 + kofs], b11 = bias[nt1 * 8 + kofs + 1];
        split2(C[nt0][0] + b00, C[nt0][1] + b01, Af[0][ks][0], Af[1][ks][0]);
        split2(C[nt0][2] + b00, C[nt0][3] + b01, Af[0][ks][1], Af[1][ks][1]);
        split2(C[nt1][0] + b10, C[nt1][1] + b11, Af[0][ks][2], Af[1][ks][2]);
        split2(C[nt1][2] + b10, C[nt1][3] + b11, Af[0][ks][3], Af[1][ks][3]);
    }

    // ---------- Phase 2: 15 n-slabs of 64, bf16x3 HMMA; E -> gmem fp16 ----------
    auto load_B = [&](int t, int bq) {
        int n0 = t * 64;
        char* dst = smc + XS_B + bq * 18432;
#pragma unroll
        for (int it = 0; it < 4; ++it) {
            int i = it * 256 + tid; int n = i >> 4; int c = i & 15;
            float s = snorm[n0 + n];
            float4 v = *(const float4*)(emb + (size_t)(n0 + n) * DS_ + c * 4);
            uint32_t p0, p1, q0, q1;
            split2(v.x * s, v.y * s, p0, p1);
            split2(v.z * s, v.w * s, q0, q1);
            uint32_t off = (uint32_t)(n * ROWB + c * 8);
            *(uint2*)(dst + 0 * 9216 + off) = make_uint2(p0, q0);
            *(uint2*)(dst + 1 * 9216 + off) = make_uint2(p1, q1);
        }
    };

    float zacc[2][4] = {{0.f, 0.f, 0.f, 0.f}, {0.f, 0.f, 0.f, 0.f}};

    load_B(0, 0);
    __syncthreads();

    for (int t = 0; t < 15; ++t) {
        if (t + 1 < 15) load_B(t + 1, (t + 1) & 1);
        uint32_t bb = sbase + XS_B + (uint32_t)((t & 1) * 18432);
        int g = (t < 8) ? 0 : (t < 12) ? 1 : (t < 14) ? 2 : 3;

#pragma unroll
        for (int nt = 0; nt < 8; ++nt) {
            uint32_t Bf[2][4][2];
#pragma unroll
            for (int s = 0; s < 2; s++)
#pragma unroll
                for (int kp = 0; kp < 2; kp++)
                    ldsm_x4(Bf[s][2 * kp][0], Bf[s][2 * kp][1],
                            Bf[s][2 * kp + 1][0], Bf[s][2 * kp + 1][1],
                            bb + s * 9216 + (uint32_t)((nt * 8 + brow) * ROWB
                                                       + (kp * 32 + bcolq) * 2));
            float Cp[3][4];
#pragma unroll
            for (int p = 0; p < 3; p++)
#pragma unroll
                for (int j = 0; j < 4; j++) Cp[p][j] = 0.f;
#pragma unroll
            for (int ks = 0; ks < 4; ks++) {
                mma_bf16(Cp[0], Af[0][ks], Bf[0][ks]);
                mma_bf16(Cp[1], Af[0][ks], Bf[1][ks]);
                mma_bf16(Cp[2], Af[1][ks], Bf[0][ks]);
            }
            float c0 = Cp[0][0] + (Cp[1][0] + Cp[2][0]);
            float c1 = Cp[0][1] + (Cp[1][1] + Cp[2][1]);
            float c2 = Cp[0][2] + (Cp[1][2] + Cp[2][2]);
            float c3 = Cp[0][3] + (Cp[1][3] + Cp[2][3]);

            float e0 = fexp(c0), e1 = fexp(c1);
            float e2 = fexp(c2), e3 = fexp(c3);
            int col = t * 64 + nt * 8 + kofs;
            __half2 h01 = __float22half2_rn(make_float2(e0, e1));
            __half2 h23 = __float22half2_rn(make_float2(e2, e3));
            *(uint32_t*)(g_Eh + (size_t)(m0 + row0) * NU + col)     = *(uint32_t*)&h01;
            *(uint32_t*)(g_Eh + (size_t)(m0 + row0 + 8) * NU + col) = *(uint32_t*)&h23;
            zacc[0][g] += e0 + e1;
            zacc[1][g] += e2 + e3;
        }
        __syncthreads();   // buf t consumed; buf t+1 committed
    }

    // ---------- row Z: quad-reduce, write sZ ----------
#pragma unroll
    for (int h = 0; h < 2; h++)
#pragma unroll
        for (int g = 0; g < 4; g++) {
            float z = zacc[h][g];
            z += __shfl_xor_sync(0xffffffffu, z, 1);
            z += __shfl_xor_sync(0xffffffffu, z, 2);
            zacc[h][g] = z;
        }
    if ((lane & 3) == 0) {
#pragma unroll
        for (int g = 0; g < 4; g++) {
            sZ[row0 * 4 + g]       = zacc[0][g];
            sZ[(row0 + 8) * 4 + g] = zacc[1][g];
        }
    }
    __syncthreads();

    // ---------- coef = imp / Z ----------
    if (tid < 128) {
        float im = imp[m0 + tid];
#pragma unroll
        for (int g = 0; g < 4; g++) scoef[tid * 4 + g] = im * __frcp_rn(sZ[tid * 4 + g]);
    }
    __syncthreads();   // scoef ready; g_Eh writes visible block-wide

    // ---------- Phase 4: accum -> wpart[bx][960] ----------
    if (tid < 240) {
        int n4 = tid * 4;
        int g = (n4 < 512) ? 0 : (n4 < 768) ? 1 : (n4 < 896) ? 2 : 3;
        float4 a = make_float4(0.f, 0.f, 0.f, 0.f);
#pragma unroll 4
        for (int r = 0; r < 128; r++) {
            float cf = scoef[r * 4 + g];
            uint2 hh = *(const uint2*)(g_Eh + (size_t)(m0 + r) * NU + n4);
            float2 f01 = __half22float2(*reinterpret_cast<__half2*>(&hh.x));
            float2 f23 = __half22float2(*reinterpret_cast<__half2*>(&hh.y));
            a.x += cf * f01.x; a.y += cf * f01.y;
            a.z += cf * f23.x; a.w += cf * f23.y;
        }
        *(float4*)(g_wpart + (size_t)blockIdx.x * NU + n4) = a;
    }
}

// ---------------- k_final: parallel rank-select top-k ----------------
__global__ __launch_bounds__(512) void k_final(float* __restrict__ out) {
    __shared__ __align__(16) float sw[NU];
    __shared__ unsigned bq[16];
    __shared__ unsigned bv[8];
    int b = blockIdx.x, t = threadIdx.x;
    int w = t >> 5, lane = t & 31;

    for (int n = t; n < NU; n += 512) {
        float a = 0.f;
#pragma unroll
        for (int c = 0; c < 32; c++) a += g_wpart[(size_t)(b * 32 + c) * NU + n];
        sw[n] = a;
    }
    __syncthreads();

    const float4* s4 = (const float4*)sw;
    bool selq;
    {
        float v = sw[t]; int r = 0;
#pragma unroll 4
        for (int j4 = 0; j4 < 128; j4++) {
            float4 o = s4[j4]; int j = j4 * 4;
            r += (o.x > v) || (o.x == v && j < t);
            r += (o.y > v) || (o.y == v && j + 1 < t);
            r += (o.z > v) || (o.z == v && j + 2 < t);
            r += (o.w > v) || (o.w == v && j + 3 < t);
        }
        selq = (r < 64);
    }
    bool selv = false, selr = false, selval = false;
    if (t < 256) {
        float v = sw[512 + t]; int r = 0;
#pragma unroll 4
        for (int j4 = 0; j4 < 64; j4++) {
            float4 o = s4[128 + j4]; int j = j4 * 4;
            r += (o.x > v) || (o.x == v && j < t);
            r += (o.y > v) || (o.y == v && j + 1 < t);
            r += (o.z > v) || (o.z == v && j + 2 < t);
            r += (o.w > v) || (o.w == v && j + 3 < t);
        }
        selv = (r < 32);
    }
    if (t < 128) {
        float v = sw[768 + t]; int r = 0;
#pragma unroll 4
        for (int j4 = 0; j4 < 32; j4++) {
            float4 o = s4[192 + j4]; int j = j4 * 4;
            r += (o.x > v) || (o.x == v && j < t);
            r += (o.y > v) || (o.y == v && j + 1 < t);
            r += (o.z > v) || (o.z == v && j + 2 < t);
            r += (o.w > v) || (o.w == v && j + 3 < t);
        }
        selr = (r < 16);
    }
    if (t < 64) {
        float v = sw[896 + t]; int r = 0;
#pragma unroll
        for (int j4 = 0; j4 < 16; j4++) {
            float4 o = s4[224 + j4]; int j = j4 * 4;
            r += (o.x > v) || (o.x == v && j < t);
            r += (o.y > v) || (o.y == v && j + 1 < t);
            r += (o.z > v) || (o.z == v && j + 2 < t);
            r += (o.w > v) || (o.w == v && j + 3 < t);
        }
        selval = (r < 3);
    }

    unsigned mq = __ballot_sync(0xffffffffu, selq);
    unsigned mv = __ballot_sync(0xffffffffu, selv);
    if (lane == 0) {
        bq[w] = mq;
        if (w < 8) bv[w] = mv;
    }
    __syncthreads();

    if (selq) {
        int pos = 0;
        for (int i = 0; i < w; i++) pos += __popc(bq[i]);
        pos += __popc(mq & ((1u << lane) - 1u));
        out[b * 64 + pos] = (float)t;
    }
    if (selv) {
        int pos = 0;
        for (int i = 0; i < w; i++) pos += __popc(bv[i]);
        pos += __popc(mv & ((1u << lane) - 1u));
        out[512 + b * 32 + pos] = (float)t;
    }
    if (t < 128) {
        float val = selr ? sw[768 + t] : 0.f;
        out[768  + b * 128 + t] = val;
        out[1792 + b * 128 + t] = val;
    }
    if (t < 64) {
        out[2816 + b * 64 + t] = selval ? sw[896 + t] : 0.f;
    }
}

// ---------------- launch ----------------
extern "C" void kernel_launch(void* const* d_in, const int* in_sizes, int n_in,
                              void* d_out, int out_size) {
    const float* x    = (const float*)d_in[0];
    const float* imp  = (const float*)d_in[1];
    const float* W    = (const float*)d_in[2];
    const float* bias = (const float*)d_in[3];
    const float* emb  = (const float*)d_in[4];
    float* out = (float*)d_out;

    static bool attr_set = false;
    if (!attr_set) {
        cudaFuncSetAttribute(k_mega, cudaFuncAttributeMaxDynamicSharedMemorySize,
                             SMEM_BYTES);
        attr_set = true;
    }

    k_mega<<<NBLK, 256, SMEM_BYTES>>>(x, W, bias, imp, emb);
    k_final<<<B_, 512>>>(out);
}